// round 3
// baseline (speedup 1.0000x reference)
#include <cuda_runtime.h>
#include <cuda_bf16.h>

// GaussianRender: 64 tiles (8x8) of 64x64 px, K=256 sorted gaussians/tile.
// Issue-bound kernel: Blackwell packed f32x2 FMA/MUL/ADD, 4 px/thread as two
// packed pairs; 1024 CTAs x 64 thr for SM balance.
// NOTE: reference transmittance is ARITHMETIC: trans_k = 1 - sum_{j<k} alpha_j
// (trans -= alpha), NOT the multiplicative trans *= (1-alpha).

#define NTILE  8
#define TS     64
#define KG     256
#define WIMG   512

union F2U { float2 f; unsigned long long u; };

__device__ __forceinline__ float2 ffma2(float2 a, float2 b, float2 c) {
    F2U A, B, C, D; A.f = a; B.f = b; C.f = c;
    asm("fma.rn.f32x2 %0, %1, %2, %3;" : "=l"(D.u) : "l"(A.u), "l"(B.u), "l"(C.u));
    return D.f;
}
__device__ __forceinline__ float2 fmul2(float2 a, float2 b) {
    F2U A, B, D; A.f = a; B.f = b;
    asm("mul.rn.f32x2 %0, %1, %2;" : "=l"(D.u) : "l"(A.u), "l"(B.u));
    return D.f;
}
__device__ __forceinline__ float2 fadd2(float2 a, float2 b) {
    F2U A, B, D; A.f = a; B.f = b;
    asm("add.rn.f32x2 %0, %1, %2;" : "=l"(D.u) : "l"(A.u), "l"(B.u));
    return D.f;
}
__device__ __forceinline__ float ex2f(float x) {
    float y; asm("ex2.approx.f32 %0, %1;" : "=f"(y) : "f"(x)); return y;
}
__device__ __forceinline__ float lg2f(float x) {
    float y; asm("lg2.approx.f32 %0, %1;" : "=f"(y) : "f"(x)); return y;
}

__global__ __launch_bounds__(64, 16)
void GaussianRender_kernel(const float* __restrict__ mu,
                           const float* __restrict__ cov,
                           const float* __restrict__ opac,
                           const float* __restrict__ col,
                           const int*   __restrict__ tidx,
                           float*       __restrict__ out)
{
    __shared__ float4 sA[KG];   // mx, my, k1, k2
    __shared__ float4 sB[KG];   // k3, k3, cr, cr   (pre-duplicated for f32x2)
    __shared__ float4 sC[KG];   // cg, cg, cb, cb
    __shared__ float  sL[KG];   // log2(opacity)

    const int bid = blockIdx.x;
    const int t   = bid >> 4;        // tile id 0..63
    const int s   = bid & 15;        // 4-row segment within tile
    const int tx  = t & (NTILE - 1);
    const int ty  = t >> 3;
    const int tid = threadIdx.x;     // 0..63 = column within tile

    // ---- preprocess: 4 gaussians per thread into smem ----
    #pragma unroll
    for (int i = 0; i < 4; ++i) {
        const int j = tid + 64 * i;
        const int g = tidx[t * KG + j];
        const float4 cv = *(const float4*)(cov + g * 4);
        const float2 m  = *(const float2*)(mu + g * 2);
        const float det = fmaxf(fmaf(cv.x, cv.w, -cv.y * cv.z), 1e-6f);
        const float inv = 1.0f / det;
        const float e  = -0.7213475204444817f;   // -0.5 * log2(e)
        const float k1 = e * cv.w * inv;
        const float k2 = -e * (cv.y + cv.z) * inv;
        const float k3 = e * cv.x * inv;
        const float cr = col[g * 3 + 0];
        const float cg = col[g * 3 + 1];
        const float cb = col[g * 3 + 2];
        sA[j] = make_float4(m.x, m.y, k1, k2);
        sB[j] = make_float4(k3, k3, cr, cr);
        sC[j] = make_float4(cg, cg, cb, cb);
        sL[j] = lg2f(opac[g]);
    }
    __syncthreads();

    // 4 pixels per thread: column (tx*64+tid), rows (ty*64 + s*4 + {0,1,2,3})
    const float px  = (float)(tx * TS + tid) + 0.5f;
    const float py0 = (float)(ty * TS + s * 4) + 0.5f;

    float2 accR0 = {0.f,0.f}, accG0 = {0.f,0.f}, accB0 = {0.f,0.f};
    float2 accR1 = {0.f,0.f}, accG1 = {0.f,0.f}, accB1 = {0.f,0.f};
    float2 trA   = {1.f,1.f}, trB   = {1.f,1.f};
    const float2 m1  = make_float2(-1.f, -1.f);
    const float2 c01 = make_float2( 0.f,  1.f);
    const float2 c23 = make_float2( 2.f,  3.f);

    #pragma unroll 4
    for (int k = 0; k < KG; ++k) {
        const float4 A = sA[k];
        const float4 B = sB[k];
        const float4 C = sC[k];
        const float  lop = sL[k];

        const float dx = px - A.x;
        const float u  = fmaf(A.z * dx, dx, lop);   // k1*dx^2 + log2(op)
        const float kx = A.w * dx;                  // k2*dx
        const float dy = py0 - A.y;

        const float2 u2  = make_float2(u, u);
        const float2 kx2 = make_float2(kx, kx);
        const float2 dy2 = make_float2(dy, dy);
        const float2 k32 = make_float2(B.x, B.y);
        const float2 crr = make_float2(B.z, B.w);
        const float2 cgg = make_float2(C.x, C.y);
        const float2 cbb = make_float2(C.z, C.w);

        const float2 dyA = fadd2(dy2, c01);         // rows +0,+1
        const float2 dyB = fadd2(dy2, c23);         // rows +2,+3

        const float2 qA = ffma2(k32, dyA, kx2);     // k3*dy + k2*dx
        const float2 pA = ffma2(dyA, qA, u2);       // log2-domain exponent
        const float2 qB = ffma2(k32, dyB, kx2);
        const float2 pB = ffma2(dyB, qB, u2);

        float a0 = ex2f(pA.x), a1 = ex2f(pA.y);
        float a2 = ex2f(pB.x), a3 = ex2f(pB.y);
        a0 = fminf(fmaxf(a0, 0.01f), 0.99f);
        a1 = fminf(fmaxf(a1, 0.01f), 0.99f);
        a2 = fminf(fmaxf(a2, 0.01f), 0.99f);
        a3 = fminf(fmaxf(a3, 0.01f), 0.99f);

        const float2 alA = make_float2(a0, a1);
        const float2 alB = make_float2(a2, a3);
        const float2 wA  = fmul2(alA, trA);         // w = alpha * (1 - sum_prev)
        const float2 wB  = fmul2(alB, trB);
        trA = ffma2(alA, m1, trA);                  // trans -= alpha  (cumsum!)
        trB = ffma2(alB, m1, trB);

        accR0 = ffma2(wA, crr, accR0);
        accG0 = ffma2(wA, cgg, accG0);
        accB0 = ffma2(wA, cbb, accB0);
        accR1 = ffma2(wB, crr, accR1);
        accG1 = ffma2(wB, cgg, accG1);
        accB1 = ffma2(wB, cbb, accB1);
    }

    // ---- write 4 pixels (rows gy..gy+3, column gx) ----
    const int gx = tx * TS + tid;
    const int gy = ty * TS + s * 4;
    float* o = out + ((size_t)gy * WIMG + gx) * 3;
    o[0] = accR0.x; o[1] = accG0.x; o[2] = accB0.x;  o += WIMG * 3;
    o[0] = accR0.y; o[1] = accG0.y; o[2] = accB0.y;  o += WIMG * 3;
    o[0] = accR1.x; o[1] = accG1.x; o[2] = accB1.x;  o += WIMG * 3;
    o[0] = accR1.y; o[1] = accG1.y; o[2] = accB1.y;
}

extern "C" void kernel_launch(void* const* d_in, const int* in_sizes, int n_in,
                              void* d_out, int out_size)
{
    const float* mu   = (const float*)d_in[0];
    const float* cov  = (const float*)d_in[1];
    const float* opac = (const float*)d_in[2];
    const float* col  = (const float*)d_in[3];
    const int*   tidx = (const int*)  d_in[4];
    float* out = (float*)d_out;

    // 64 tiles * 16 row-segments = 1024 blocks, 64 threads, 4 px/thread
    GaussianRender_kernel<<<1024, 64>>>(mu, cov, opac, col, tidx, out);
}

// round 4
// speedup vs baseline: 1.0956x; 1.0956x over previous
#include <cuda_runtime.h>
#include <cuda_bf16.h>

// GaussianRender: 64 tiles (8x8) of 64x64 px, K=256 sorted gaussians/tile.
// Packed f32x2 math, 4 px/thread (1 column x 4 rows as two packed pairs).
// 512 CTAs x 128 threads -> all 4 SMSPs populated (wid%4 SMSP mapping!).
// All per-gaussian constants pre-duplicated into 64-bit lanes in smem so
// packed ops consume LDS.128 register pairs directly (no splat MOVs).
// Transmittance is ARITHMETIC cumsum: trans -= alpha.

#define NTILE  8
#define TS     64
#define KG     256
#define WIMG   512

typedef unsigned long long u64;
union F2U { float2 f; u64 u; };

__device__ __forceinline__ u64 pk(float a, float b) { F2U t; t.f = make_float2(a, b); return t.u; }
__device__ __forceinline__ u64 ffma2(u64 a, u64 b, u64 c) {
    u64 d; asm("fma.rn.f32x2 %0, %1, %2, %3;" : "=l"(d) : "l"(a), "l"(b), "l"(c)); return d;
}
__device__ __forceinline__ u64 fmul2(u64 a, u64 b) {
    u64 d; asm("mul.rn.f32x2 %0, %1, %2;" : "=l"(d) : "l"(a), "l"(b)); return d;
}
__device__ __forceinline__ u64 fadd2(u64 a, u64 b) {
    u64 d; asm("add.rn.f32x2 %0, %1, %2;" : "=l"(d) : "l"(a), "l"(b)); return d;
}
__device__ __forceinline__ float ex2f(float x) {
    float y; asm("ex2.approx.f32 %0, %1;" : "=f"(y) : "f"(x)); return y;
}
__device__ __forceinline__ float lg2f(float x) {
    float y; asm("lg2.approx.f32 %0, %1;" : "=f"(y) : "f"(x)); return y;
}
__device__ __forceinline__ float clampa(float a) {
    return fminf(fmaxf(a, 0.01f), 0.99f);
}

__global__ __launch_bounds__(128, 8)
void GaussianRender_kernel(const float* __restrict__ mu,
                           const float* __restrict__ cov,
                           const float* __restrict__ opac,
                           const float* __restrict__ col,
                           const int*   __restrict__ tidx,
                           float*       __restrict__ out)
{
    // Per-gaussian constants, each duplicated into both 32-bit halves.
    __shared__ ulonglong2 s0[KG];   // {-mx,-mx}, {-my,-my}
    __shared__ ulonglong2 s1[KG];   // {k1,k1},  {k2,k2}
    __shared__ ulonglong2 s2[KG];   // {k3,k3},  {lop,lop}
    __shared__ ulonglong2 s3[KG];   // {cr,cr},  {cg,cg}
    __shared__ u64        s4[KG];   // {cb,cb}

    const int bid = blockIdx.x;
    const int t   = bid >> 3;        // tile 0..63
    const int s   = bid & 7;         // 8-row segment within tile
    const int tx  = t & (NTILE - 1);
    const int ty  = t >> 3;
    const int tid = threadIdx.x;     // 0..127

    // ---- preprocess: 2 gaussians per thread ----
    #pragma unroll
    for (int i = 0; i < 2; ++i) {
        const int j = tid + 128 * i;
        const int g = tidx[t * KG + j];
        const float4 cv = *(const float4*)(cov + g * 4);
        const float2 m  = *(const float2*)(mu + g * 2);
        const float det = fmaxf(fmaf(cv.x, cv.w, -cv.y * cv.z), 1e-6f);
        const float inv = 1.0f / det;
        const float e  = -0.7213475204444817f;   // -0.5 * log2(e)
        const float k1 = e * cv.w * inv;
        const float k2 = -e * (cv.y + cv.z) * inv;
        const float k3 = e * cv.x * inv;
        const float lop = lg2f(opac[g]);
        s0[j] = make_ulonglong2(pk(-m.x, -m.x), pk(-m.y, -m.y));
        s1[j] = make_ulonglong2(pk(k1, k1), pk(k2, k2));
        s2[j] = make_ulonglong2(pk(k3, k3), pk(lop, lop));
        s3[j] = make_ulonglong2(pk(col[g*3+0], col[g*3+0]), pk(col[g*3+1], col[g*3+1]));
        s4[j] = pk(col[g*3+2], col[g*3+2]);
    }
    __syncthreads();

    // 4 pixels/thread: column (tx*64 + tid&63), rows ty*64 + s*8 + (tid>>6)*4 + {0..3}
    const int lx  = tid & 63;
    const int ly0 = s * 8 + (tid >> 6) * 4;
    const float px  = (float)(tx * TS + lx) + 0.5f;
    const float py0 = (float)(ty * TS + ly0) + 0.5f;

    const u64 px2 = pk(px, px);
    const u64 pyA = pk(py0,        py0 + 1.f);
    const u64 pyB = pk(py0 + 2.f,  py0 + 3.f);
    const u64 m1  = pk(-1.f, -1.f);

    u64 accR0 = 0, accG0 = 0, accB0 = 0;
    u64 accR1 = 0, accG1 = 0, accB1 = 0;
    u64 trA = pk(1.f, 1.f), trB = pk(1.f, 1.f);

    #pragma unroll 4
    for (int k = 0; k < KG; ++k) {
        const ulonglong2 v0 = s0[k];   // nmx, nmy
        const ulonglong2 v1 = s1[k];   // k1,  k2
        const ulonglong2 v2 = s2[k];   // k3,  lop
        const ulonglong2 v3 = s3[k];   // cr,  cg
        const u64        cb = s4[k];

        const u64 dx2 = fadd2(px2, v0.x);
        const u64 t0  = fmul2(v1.x, dx2);
        const u64 u2  = ffma2(t0, dx2, v2.y);   // k1*dx^2 + lop
        const u64 kx2 = fmul2(v1.y, dx2);       // k2*dx
        const u64 dyA = fadd2(pyA, v0.y);
        const u64 dyB = fadd2(pyB, v0.y);
        const u64 qA  = ffma2(v2.x, dyA, kx2);
        const u64 pA  = ffma2(dyA, qA, u2);
        const u64 qB  = ffma2(v2.x, dyB, kx2);
        const u64 pB  = ffma2(dyB, qB, u2);

        F2U uA, uB; uA.u = pA; uB.u = pB;
        F2U alA, alB;
        alA.f.x = clampa(ex2f(uA.f.x));
        alA.f.y = clampa(ex2f(uA.f.y));
        alB.f.x = clampa(ex2f(uB.f.x));
        alB.f.y = clampa(ex2f(uB.f.y));

        const u64 wA = fmul2(alA.u, trA);       // alpha * (1 - sum_prev)
        const u64 wB = fmul2(alB.u, trB);
        trA = ffma2(alA.u, m1, trA);            // trans -= alpha (cumsum)
        trB = ffma2(alB.u, m1, trB);

        accR0 = ffma2(wA, v3.x, accR0);
        accG0 = ffma2(wA, v3.y, accG0);
        accB0 = ffma2(wA, cb,   accB0);
        accR1 = ffma2(wB, v3.x, accR1);
        accG1 = ffma2(wB, v3.y, accG1);
        accB1 = ffma2(wB, cb,   accB1);
    }

    // ---- write 4 pixels (rows gy..gy+3, column gx) ----
    const int gx = tx * TS + lx;
    const int gy = ty * TS + ly0;
    F2U r0, g0, b0, r1, g1, b1;
    r0.u = accR0; g0.u = accG0; b0.u = accB0;
    r1.u = accR1; g1.u = accG1; b1.u = accB1;
    float* o = out + ((size_t)gy * WIMG + gx) * 3;
    o[0] = r0.f.x; o[1] = g0.f.x; o[2] = b0.f.x;  o += WIMG * 3;
    o[0] = r0.f.y; o[1] = g0.f.y; o[2] = b0.f.y;  o += WIMG * 3;
    o[0] = r1.f.x; o[1] = g1.f.x; o[2] = b1.f.x;  o += WIMG * 3;
    o[0] = r1.f.y; o[1] = g1.f.y; o[2] = b1.f.y;
}

extern "C" void kernel_launch(void* const* d_in, const int* in_sizes, int n_in,
                              void* d_out, int out_size)
{
    const float* mu   = (const float*)d_in[0];
    const float* cov  = (const float*)d_in[1];
    const float* opac = (const float*)d_in[2];
    const float* col  = (const float*)d_in[3];
    const int*   tidx = (const int*)  d_in[4];
    float* out = (float*)d_out;

    // 64 tiles * 8 segments = 512 blocks, 128 threads, 4 px/thread
    GaussianRender_kernel<<<512, 128>>>(mu, cov, opac, col, tidx, out);
}

// round 5
// speedup vs baseline: 1.2583x; 1.1485x over previous
#include <cuda_runtime.h>
#include <cuda_bf16.h>

// GaussianRender: 64 tiles (8x8) of 64x64 px, K=256 depth-sorted gaussians/tile.
// Key algorithmic win: alpha = clip(op*prob, 0.01, 0.99). Gaussians provably
// "far" from the entire tile (conservative log-domain bound) contribute exactly
// alpha = 0.01 to EVERY pixel. A run of m consecutive far gaussians has a
// closed form: per channel  acc += q*T0*sum(c) - q^2*sum(j*c),  T -= q*m,
// with the sums pixel-independent. The per-pixel loop collapses from 256 full
// evaluations to ~15 run/near entries.
//
// Phases per CTA (all CTAs of a tile redundantly build the same stream; cheap):
//  1. 128 threads build per-gaussian records + far flags into smem
//  2. 8 walker lanes segment their 32-gaussian ranges into entries (runs split
//     at range boundaries compose exactly)
//  3. mainloop: packed f32x2, 2 px/thread; 1024 CTAs x 128 threads.

#define KG      256
#define WIMG    512
#define NW      8       // walkers
#define RNG     32      // gaussians per walker
#define EMAX    34      // max entries per walker range (alternating worst case 33)
#define ESTR    10      // u64 per entry (80B, 16B-aligned stride)

typedef unsigned long long u64;
union F2U { float2 f; u64 u; };

__device__ __forceinline__ u64 pk(float a, float b) { F2U t; t.f = make_float2(a, b); return t.u; }
__device__ __forceinline__ u64 ffma2(u64 a, u64 b, u64 c) {
    u64 d; asm("fma.rn.f32x2 %0, %1, %2, %3;" : "=l"(d) : "l"(a), "l"(b), "l"(c)); return d;
}
__device__ __forceinline__ u64 fmul2(u64 a, u64 b) {
    u64 d; asm("mul.rn.f32x2 %0, %1, %2;" : "=l"(d) : "l"(a), "l"(b)); return d;
}
__device__ __forceinline__ u64 fadd2(u64 a, u64 b) {
    u64 d; asm("add.rn.f32x2 %0, %1, %2;" : "=l"(d) : "l"(a), "l"(b)); return d;
}
__device__ __forceinline__ float ex2f(float x) {
    float y; asm("ex2.approx.f32 %0, %1;" : "=f"(y) : "f"(x)); return y;
}
__device__ __forceinline__ float lg2f(float x) {
    float y; asm("lg2.approx.f32 %0, %1;" : "=f"(y) : "f"(x)); return y;
}
__device__ __forceinline__ float clampa(float a) { return fminf(fmaxf(a, 0.01f), 0.99f); }

__global__ __launch_bounds__(128, 7)
void GaussianRender_kernel(const float* __restrict__ mu,
                           const float* __restrict__ cov,
                           const float* __restrict__ opac,
                           const float* __restrict__ col,
                           const int*   __restrict__ tidx,
                           float*       __restrict__ out)
{
    // record: [0]=-mx [1]=-my [2]=k1 [3]=k2 [4]=k3 [5]=lop [6]=cr [7]=cg [8]=cb
    __shared__ float         rec[KG][9];
    __shared__ unsigned char sfar[KG];
    __shared__ u64           ent[NW][EMAX][ESTR];   // duplicated-lane u64 payloads
    __shared__ unsigned char stag[NW][EMAX];        // 0 = run, 1 = near
    __shared__ int           sne[NW];

    const int bid = blockIdx.x;
    const int t   = bid >> 4;        // tile 0..63
    const int s   = bid & 15;        // 4-row segment
    const int tx  = t & 7;
    const int ty  = t >> 3;
    const int tid = threadIdx.x;     // 0..127

    const float x0 = (float)(tx * 64) + 0.5f, x1 = x0 + 63.0f;
    const float y0 = (float)(ty * 64) + 0.5f, y1 = y0 + 63.0f;

    // ---- phase 1: records + conservative far classification ----
    #pragma unroll
    for (int i = 0; i < 2; ++i) {
        const int j = tid + 128 * i;
        const int g = tidx[t * KG + j];
        const float4 cv = *(const float4*)(cov + g * 4);
        const float2 m  = *(const float2*)(mu + g * 2);
        const float det = fmaxf(fmaf(cv.x, cv.w, -cv.y * cv.z), 1e-6f);
        const float inv = 1.0f / det;
        const float e  = -0.7213475204444817f;   // -0.5 * log2(e)
        const float k1 = e * cv.w * inv;                // dx^2 coeff (<=0)
        const float k2 = -e * (cv.y + cv.z) * inv;      // dx*dy coeff
        const float k3 = e * cv.x * inv;                // dy^2 coeff (<=0)
        const float lop = lg2f(opac[g]);

        // interval upper bound of log2(alpha) over the tile pixel box
        const float dlo = x0 - m.x, dhi = x1 - m.x;
        const float mdx = fmaxf(fmaxf(dlo, -dhi), 0.0f);
        const float axx = fmaxf(fabsf(dlo), fabsf(dhi));
        const float elo = y0 - m.y, ehi = y1 - m.y;
        const float mdy = fmaxf(fmaxf(elo, -ehi), 0.0f);
        const float axy = fmaxf(fabsf(elo), fabsf(ehi));
        const float bnd = k1 * mdx * mdx + k3 * mdy * mdy
                        + fabsf(k2) * axx * axy + lop;
        sfar[j] = (bnd < (-6.6438561897747395f - 0.01f)) ? 1 : 0;  // log2(0.01)-margin

        rec[j][0] = -m.x;  rec[j][1] = -m.y;
        rec[j][2] = k1;    rec[j][3] = k2;
        rec[j][4] = k3;    rec[j][5] = lop;
        rec[j][6] = col[g * 3 + 0];
        rec[j][7] = col[g * 3 + 1];
        rec[j][8] = col[g * 3 + 2];
    }
    __syncthreads();

    // ---- phase 2: 8 walkers build run/near entry streams ----
    if (tid < NW) {
        const float q = 0.01f;
        int ew = 0;
        float c1r = 0.f, c1g = 0.f, c1b = 0.f;
        float c2r = 0.f, c2g = 0.f, c2b = 0.f, cnt = 0.f;
        const int j0 = tid * RNG;
        for (int j = j0; j < j0 + RNG; ++j) {
            const float cr = rec[j][6], cg = rec[j][7], cb = rec[j][8];
            if (sfar[j]) {
                c2r = fmaf(cnt, cr, c2r);
                c2g = fmaf(cnt, cg, c2g);
                c2b = fmaf(cnt, cb, c2b);
                c1r += cr; c1g += cg; c1b += cb;
                cnt += 1.0f;
            } else {
                if (cnt > 0.0f) {
                    u64* p = ent[tid][ew];
                    p[0] = pk(q * c1r, q * c1r);
                    p[1] = pk(q * c1g, q * c1g);
                    p[2] = pk(q * c1b, q * c1b);
                    p[3] = pk(-q * q * c2r, -q * q * c2r);
                    p[4] = pk(-q * q * c2g, -q * q * c2g);
                    p[5] = pk(-q * q * c2b, -q * q * c2b);
                    p[6] = pk(-q * cnt, -q * cnt);
                    stag[tid][ew] = 0; ++ew;
                    c1r = c1g = c1b = c2r = c2g = c2b = cnt = 0.f;
                }
                u64* p = ent[tid][ew];
                #pragma unroll
                for (int r = 0; r < 9; ++r) { const float v = rec[j][r]; p[r] = pk(v, v); }
                stag[tid][ew] = 1; ++ew;
            }
        }
        if (cnt > 0.0f) {
            u64* p = ent[tid][ew];
            p[0] = pk(q * c1r, q * c1r);
            p[1] = pk(q * c1g, q * c1g);
            p[2] = pk(q * c1b, q * c1b);
            p[3] = pk(-q * q * c2r, -q * q * c2r);
            p[4] = pk(-q * q * c2g, -q * q * c2g);
            p[5] = pk(-q * q * c2b, -q * q * c2b);
            p[6] = pk(-q * cnt, -q * cnt);
            stag[tid][ew] = 0; ++ew;
        }
        sne[tid] = ew;
    }
    __syncthreads();

    // ---- phase 3: mainloop, 2 px/thread (column lx, rows gy, gy+1) ----
    const int lx = tid & 63;
    const int ry = tid >> 6;
    const float px = x0 + (float)lx;
    const float py = (float)(ty * 64 + s * 4 + ry * 2) + 0.5f;
    const u64 px2 = pk(px, px);
    const u64 py2 = pk(py, py + 1.0f);
    const u64 m1  = pk(-1.0f, -1.0f);

    u64 aR = 0, aG = 0, aB = 0;
    u64 tr = pk(1.0f, 1.0f);

    for (int w = 0; w < NW; ++w) {
        const int ne = sne[w];
        for (int e = 0; e < ne; ++e) {
            const u64* p = ent[w][e];
            if (stag[w][e]) {
                // near: full evaluation
                const u64 dx2 = fadd2(px2, p[0]);
                const u64 t0  = fmul2(p[2], dx2);
                const u64 u2  = ffma2(t0, dx2, p[5]);     // k1*dx^2 + lop
                const u64 kx2 = fmul2(p[3], dx2);         // k2*dx
                const u64 dy2 = fadd2(py2, p[1]);
                const u64 q2  = ffma2(p[4], dy2, kx2);
                const u64 pw  = ffma2(dy2, q2, u2);
                F2U P; P.u = pw;
                F2U al;
                al.f.x = clampa(ex2f(P.f.x));
                al.f.y = clampa(ex2f(P.f.y));
                const u64 wv = fmul2(al.u, tr);           // alpha*(1 - sum_prev)
                tr = ffma2(al.u, m1, tr);                 // trans -= alpha (cumsum)
                aR = ffma2(wv, p[6], aR);
                aG = ffma2(wv, p[7], aG);
                aB = ffma2(wv, p[8], aB);
            } else {
                // run of m far gaussians: acc += q*T0*C1 - q^2*C2 ; T -= q*m
                aR = ffma2(tr, p[0], aR);  aR = fadd2(aR, p[3]);
                aG = ffma2(tr, p[1], aG);  aG = fadd2(aG, p[4]);
                aB = ffma2(tr, p[2], aB);  aB = fadd2(aB, p[5]);
                tr = fadd2(tr, p[6]);
            }
        }
    }

    // ---- epilogue: write 2 pixels ----
    const int gx = tx * 64 + lx;
    const int gy = ty * 64 + s * 4 + ry * 2;
    F2U R, G, B; R.u = aR; G.u = aG; B.u = aB;
    float* o = out + ((size_t)gy * WIMG + gx) * 3;
    o[0] = R.f.x; o[1] = G.f.x; o[2] = B.f.x;
    o += WIMG * 3;
    o[0] = R.f.y; o[1] = G.f.y; o[2] = B.f.y;
}

extern "C" void kernel_launch(void* const* d_in, const int* in_sizes, int n_in,
                              void* d_out, int out_size)
{
    const float* mu   = (const float*)d_in[0];
    const float* cov  = (const float*)d_in[1];
    const float* opac = (const float*)d_in[2];
    const float* col  = (const float*)d_in[3];
    const int*   tidx = (const int*)  d_in[4];
    float* out = (float*)d_out;

    // 64 tiles * 16 segments = 1024 blocks, 128 threads, 2 px/thread
    GaussianRender_kernel<<<1024, 128>>>(mu, cov, opac, col, tidx, out);
}

// round 6
// speedup vs baseline: 1.4134x; 1.1233x over previous
#include <cuda_runtime.h>
#include <cuda_bf16.h>

// GaussianRender: 64 tiles (8x8) of 64x64 px, K=256 depth-sorted gaussians/tile.
// alpha = clip(op*prob, 0.01, 0.99): gaussians provably "far" from the whole
// tile contribute exactly alpha=0.01 to every pixel; a run of m far gaussians
// has a pixel-independent closed form. Two-kernel split:
//   A (64 CTAs): build per-tile compact run/near entry stream ONCE.
//   B (1024 CTAs): smem-load stream, packed-f32x2 mainloop, 2 px/thread.

#define KG      256
#define WIMG    512
#define NW      8
#define RNG     32
#define EMAX    34          // per-walker worst case (<=33)
#define ESTR    11          // u64 per entry: 9 payload + pad + tag
#define TMAX    (NW * EMAX) // 272 entries worst case per tile

typedef unsigned long long u64;
union F2U { float2 f; u64 u; };

__device__ u64 g_ent[64][TMAX * ESTR];   // compact streams
__device__ int g_cnt[64];

__device__ __forceinline__ u64 pk(float a, float b) { F2U t; t.f = make_float2(a, b); return t.u; }
__device__ __forceinline__ u64 ffma2(u64 a, u64 b, u64 c) {
    u64 d; asm("fma.rn.f32x2 %0, %1, %2, %3;" : "=l"(d) : "l"(a), "l"(b), "l"(c)); return d;
}
__device__ __forceinline__ u64 fmul2(u64 a, u64 b) {
    u64 d; asm("mul.rn.f32x2 %0, %1, %2;" : "=l"(d) : "l"(a), "l"(b)); return d;
}
__device__ __forceinline__ u64 fadd2(u64 a, u64 b) {
    u64 d; asm("add.rn.f32x2 %0, %1, %2;" : "=l"(d) : "l"(a), "l"(b)); return d;
}
__device__ __forceinline__ float ex2f(float x) {
    float y; asm("ex2.approx.f32 %0, %1;" : "=f"(y) : "f"(x)); return y;
}
__device__ __forceinline__ float lg2f(float x) {
    float y; asm("lg2.approx.f32 %0, %1;" : "=f"(y) : "f"(x)); return y;
}
__device__ __forceinline__ float clampa(float a) { return fminf(fmaxf(a, 0.01f), 0.99f); }

// ===================== Kernel A: per-tile stream build =====================
__global__ __launch_bounds__(256, 4)
void build_kernel(const float* __restrict__ mu,
                  const float* __restrict__ cov,
                  const float* __restrict__ opac,
                  const float* __restrict__ col,
                  const int*   __restrict__ tidx)
{
    __shared__ float         rec[KG][9];
    __shared__ unsigned char sfar[KG];
    __shared__ u64           ent[NW][EMAX][ESTR];
    __shared__ int           sne[NW];
    __shared__ int           soff[NW + 1];

    const int t   = blockIdx.x;      // tile 0..63
    const int tx  = t & 7;
    const int ty  = t >> 3;
    const int tid = threadIdx.x;     // 0..255

    const float x0 = (float)(tx * 64) + 0.5f, x1 = x0 + 63.0f;
    const float y0 = (float)(ty * 64) + 0.5f, y1 = y0 + 63.0f;

    // ---- preprocess: one gaussian per thread ----
    {
        const int j = tid;
        const int g = tidx[t * KG + j];
        const float4 cv = *(const float4*)(cov + g * 4);
        const float2 m  = *(const float2*)(mu + g * 2);
        const float det = fmaxf(fmaf(cv.x, cv.w, -cv.y * cv.z), 1e-6f);
        const float inv = 1.0f / det;
        const float e  = -0.7213475204444817f;   // -0.5 * log2(e)
        const float k1 = e * cv.w * inv;
        const float k2 = -e * (cv.y + cv.z) * inv;
        const float k3 = e * cv.x * inv;
        const float lop = lg2f(opac[g]);

        // conservative upper bound of log2(alpha) over the tile box
        const float dlo = x0 - m.x, dhi = x1 - m.x;
        const float mdx = fmaxf(fmaxf(dlo, -dhi), 0.0f);
        const float axx = fmaxf(fabsf(dlo), fabsf(dhi));
        const float elo = y0 - m.y, ehi = y1 - m.y;
        const float mdy = fmaxf(fmaxf(elo, -ehi), 0.0f);
        const float axy = fmaxf(fabsf(elo), fabsf(ehi));
        const float bnd = k1 * mdx * mdx + k3 * mdy * mdy
                        + fabsf(k2) * axx * axy + lop;
        sfar[j] = (bnd < (-6.6438561897747395f - 0.01f)) ? 1 : 0;

        rec[j][0] = -m.x;  rec[j][1] = -m.y;
        rec[j][2] = k1;    rec[j][3] = k2;
        rec[j][4] = k3;    rec[j][5] = lop;
        rec[j][6] = col[g * 3 + 0];
        rec[j][7] = col[g * 3 + 1];
        rec[j][8] = col[g * 3 + 2];
    }
    __syncthreads();

    // ---- walkers: build run/near entries (tag stored in slot 9) ----
    if (tid < NW) {
        const float q = 0.01f;
        int ew = 0;
        float c1r = 0.f, c1g = 0.f, c1b = 0.f;
        float c2r = 0.f, c2g = 0.f, c2b = 0.f, cnt = 0.f;
        const int j0 = tid * RNG;
        for (int j = j0; j < j0 + RNG; ++j) {
            const float cr = rec[j][6], cg = rec[j][7], cb = rec[j][8];
            if (sfar[j]) {
                c2r = fmaf(cnt, cr, c2r);
                c2g = fmaf(cnt, cg, c2g);
                c2b = fmaf(cnt, cb, c2b);
                c1r += cr; c1g += cg; c1b += cb;
                cnt += 1.0f;
            } else {
                if (cnt > 0.0f) {
                    u64* p = ent[tid][ew];
                    p[0] = pk(q * c1r, q * c1r);
                    p[1] = pk(q * c1g, q * c1g);
                    p[2] = pk(q * c1b, q * c1b);
                    p[3] = pk(-q * q * c2r, -q * q * c2r);
                    p[4] = pk(-q * q * c2g, -q * q * c2g);
                    p[5] = pk(-q * q * c2b, -q * q * c2b);
                    p[6] = pk(-q * cnt, -q * cnt);
                    p[9] = 0ull; ++ew;
                    c1r = c1g = c1b = c2r = c2g = c2b = cnt = 0.f;
                }
                u64* p = ent[tid][ew];
                #pragma unroll
                for (int r = 0; r < 9; ++r) { const float v = rec[j][r]; p[r] = pk(v, v); }
                p[9] = 1ull; ++ew;
            }
        }
        if (cnt > 0.0f) {
            u64* p = ent[tid][ew];
            p[0] = pk(q * c1r, q * c1r);
            p[1] = pk(q * c1g, q * c1g);
            p[2] = pk(q * c1b, q * c1b);
            p[3] = pk(-q * q * c2r, -q * q * c2r);
            p[4] = pk(-q * q * c2g, -q * q * c2g);
            p[5] = pk(-q * q * c2b, -q * q * c2b);
            p[6] = pk(-q * cnt, -q * cnt);
            p[9] = 0ull; ++ew;
        }
        sne[tid] = ew;
    }
    __syncthreads();

    // ---- compact into global stream ----
    if (tid == 0) {
        int a = 0;
        #pragma unroll
        for (int w = 0; w < NW; ++w) { soff[w] = a; a += sne[w]; }
        soff[NW] = a;
        g_cnt[t] = a;
    }
    __syncthreads();

    for (int w = 0; w < NW; ++w) {
        const int n = (soff[w + 1] - soff[w]) * ESTR;
        u64* dst = g_ent[t] + soff[w] * ESTR;
        const u64* src = &ent[w][0][0];
        for (int i = tid; i < n; i += 256) dst[i] = src[i];
    }
}

// ===================== Kernel B: pixel mainloop =====================
__global__ __launch_bounds__(128, 7)
void render_kernel(float* __restrict__ out)
{
    __shared__ u64 sent[TMAX * ESTR];   // worst case 272*11*8 = 23.9KB

    const int bid = blockIdx.x;
    const int t   = bid >> 4;        // tile
    const int s   = bid & 15;        // 4-row segment
    const int tx  = t & 7;
    const int ty  = t >> 3;
    const int tid = threadIdx.x;

    const int cnt = g_cnt[t];
    const int nu  = cnt * ESTR;
    const u64* gsrc = g_ent[t];
    for (int i = tid; i < nu; i += 128) sent[i] = gsrc[i];
    __syncthreads();

    // 2 px/thread: column lx, rows gy, gy+1
    const int lx = tid & 63;
    const int ry = tid >> 6;
    const float px = (float)(tx * 64 + lx) + 0.5f;
    const float py = (float)(ty * 64 + s * 4 + ry * 2) + 0.5f;
    const u64 px2 = pk(px, px);
    const u64 py2 = pk(py, py + 1.0f);
    const u64 m1  = pk(-1.0f, -1.0f);

    u64 aR = 0, aG = 0, aB = 0;
    u64 tr = pk(1.0f, 1.0f);

    const u64* p = sent;
    for (int e = 0; e < cnt; ++e, p += ESTR) {
        if (p[9]) {
            // near: full evaluation
            const u64 dx2 = fadd2(px2, p[0]);
            const u64 t0  = fmul2(p[2], dx2);
            const u64 u2  = ffma2(t0, dx2, p[5]);     // k1*dx^2 + lop
            const u64 kx2 = fmul2(p[3], dx2);         // k2*dx
            const u64 dy2 = fadd2(py2, p[1]);
            const u64 q2  = ffma2(p[4], dy2, kx2);
            const u64 pw  = ffma2(dy2, q2, u2);
            F2U P; P.u = pw;
            F2U al;
            al.f.x = clampa(ex2f(P.f.x));
            al.f.y = clampa(ex2f(P.f.y));
            const u64 wv = fmul2(al.u, tr);           // alpha*(1 - sum_prev)
            tr = ffma2(al.u, m1, tr);                 // trans -= alpha (cumsum)
            aR = ffma2(wv, p[6], aR);
            aG = ffma2(wv, p[7], aG);
            aB = ffma2(wv, p[8], aB);
        } else {
            // run: acc += q*T0*C1 - q^2*C2 ; T -= q*m
            aR = ffma2(tr, p[0], aR);  aR = fadd2(aR, p[3]);
            aG = ffma2(tr, p[1], aG);  aG = fadd2(aG, p[4]);
            aB = ffma2(tr, p[2], aB);  aB = fadd2(aB, p[5]);
            tr = fadd2(tr, p[6]);
        }
    }

    // write 2 pixels
    const int gx = tx * 64 + lx;
    const int gy = ty * 64 + s * 4 + ry * 2;
    F2U R, G, B; R.u = aR; G.u = aG; B.u = aB;
    float* o = out + ((size_t)gy * WIMG + gx) * 3;
    o[0] = R.f.x; o[1] = G.f.x; o[2] = B.f.x;
    o += WIMG * 3;
    o[0] = R.f.y; o[1] = G.f.y; o[2] = B.f.y;
}

extern "C" void kernel_launch(void* const* d_in, const int* in_sizes, int n_in,
                              void* d_out, int out_size)
{
    const float* mu   = (const float*)d_in[0];
    const float* cov  = (const float*)d_in[1];
    const float* opac = (const float*)d_in[2];
    const float* col  = (const float*)d_in[3];
    const int*   tidx = (const int*)  d_in[4];
    float* out = (float*)d_out;

    build_kernel<<<64, 256>>>(mu, cov, opac, col, tidx);
    render_kernel<<<1024, 128>>>(out);
}

// round 7
// speedup vs baseline: 2.6027x; 1.8414x over previous
#include <cuda_runtime.h>
#include <cuda_bf16.h>

// GaussianRender: 64 tiles (8x8) of 64x64 px, K=256 depth-sorted gaussians/tile.
// alpha = clip(op*prob, 0.01, 0.99): gaussians provably "far" from the whole
// tile contribute exactly alpha=0.01 to every pixel; a run of m far gaussians
// has a pixel-independent closed form (cumsum transmittance).
// Far test (tight + conservative, Schur complement): for SPD cov,
//   maha >= dx^2/cov_xx  and  maha >= dy^2/cov_yy
// => log2(alpha) <= lop + min(e*mdx^2/a, e*mdy^2/d),  e = -0.5*log2(e),
// with mdx = min |x - mu_x| over the tile box. No cross-term cancellation.
//
//   Kernel A (64 CTAs): build per-tile compact run/near entry stream once.
//   Kernel B (1024 CTAs): smem-load stream, packed-f32x2 mainloop, 2 px/thr.

#define KG      256
#define WIMG    512
#define NW      16
#define RNG     16
#define EMAX    18          // per-walker worst case (RNG nears + trailing run)
#define ESTR    11          // u64 per entry: 9 payload + pad + tag
#define TMAX    (NW * EMAX) // 288

typedef unsigned long long u64;
union F2U { float2 f; u64 u; };

__device__ u64 g_ent[64][TMAX * ESTR];
__device__ int g_cnt[64];

__device__ __forceinline__ u64 pk(float a, float b) { F2U t; t.f = make_float2(a, b); return t.u; }
__device__ __forceinline__ u64 ffma2(u64 a, u64 b, u64 c) {
    u64 d; asm("fma.rn.f32x2 %0, %1, %2, %3;" : "=l"(d) : "l"(a), "l"(b), "l"(c)); return d;
}
__device__ __forceinline__ u64 fmul2(u64 a, u64 b) {
    u64 d; asm("mul.rn.f32x2 %0, %1, %2;" : "=l"(d) : "l"(a), "l"(b)); return d;
}
__device__ __forceinline__ u64 fadd2(u64 a, u64 b) {
    u64 d; asm("add.rn.f32x2 %0, %1, %2;" : "=l"(d) : "l"(a), "l"(b)); return d;
}
__device__ __forceinline__ float ex2f(float x) {
    float y; asm("ex2.approx.f32 %0, %1;" : "=f"(y) : "f"(x)); return y;
}
__device__ __forceinline__ float lg2f(float x) {
    float y; asm("lg2.approx.f32 %0, %1;" : "=f"(y) : "f"(x)); return y;
}
__device__ __forceinline__ float clampa(float a) { return fminf(fmaxf(a, 0.01f), 0.99f); }

// ===================== Kernel A: per-tile stream build =====================
__global__ __launch_bounds__(256, 4)
void build_kernel(const float* __restrict__ mu,
                  const float* __restrict__ cov,
                  const float* __restrict__ opac,
                  const float* __restrict__ col,
                  const int*   __restrict__ tidx)
{
    __shared__ float         rec[KG][9];
    __shared__ unsigned char sfar[KG];
    __shared__ u64           ent[NW][EMAX][ESTR];
    __shared__ int           sne[NW];
    __shared__ int           soff[NW + 1];

    const int t   = blockIdx.x;      // tile 0..63
    const int tx  = t & 7;
    const int ty  = t >> 3;
    const int tid = threadIdx.x;     // 0..255

    const float x0 = (float)(tx * 64) + 0.5f, x1 = x0 + 63.0f;
    const float y0 = (float)(ty * 64) + 0.5f, y1 = y0 + 63.0f;

    // ---- preprocess: one gaussian per thread ----
    {
        const int j = tid;
        const int g = tidx[t * KG + j];
        const float4 cv = *(const float4*)(cov + g * 4);
        const float2 m  = *(const float2*)(mu + g * 2);
        const float det = fmaxf(fmaf(cv.x, cv.w, -cv.y * cv.z), 1e-6f);
        const float inv = 1.0f / det;
        const float e  = -0.7213475204444817f;   // -0.5 * log2(e)
        const float k1 = e * cv.w * inv;
        const float k2 = -e * (cv.y + cv.z) * inv;
        const float k3 = e * cv.x * inv;
        const float lop = lg2f(opac[g]);

        // tight directional bound: log2(alpha) <= lop + min(e*mdx^2/a, e*mdy^2/d)
        const float dlo = x0 - m.x, dhi = x1 - m.x;
        const float mdx = fmaxf(fmaxf(dlo, -dhi), 0.0f);   // min |dx| over box
        const float elo = y0 - m.y, ehi = y1 - m.y;
        const float mdy = fmaxf(fmaxf(elo, -ehi), 0.0f);
        const float bx = __fdividef(e * mdx * mdx, cv.x);  // a = cov_xx >= 4
        const float by = __fdividef(e * mdy * mdy, cv.w);  // d = cov_yy >= 4
        const float bnd = fminf(bx, by) + lop;
        sfar[j] = (bnd < (-6.6438561897747395f - 0.01f)) ? 1 : 0;  // log2(0.01)-margin

        rec[j][0] = -m.x;  rec[j][1] = -m.y;
        rec[j][2] = k1;    rec[j][3] = k2;
        rec[j][4] = k3;    rec[j][5] = lop;
        rec[j][6] = col[g * 3 + 0];
        rec[j][7] = col[g * 3 + 1];
        rec[j][8] = col[g * 3 + 2];
    }
    __syncthreads();

    // ---- walkers: build run/near entries (tag in slot 9) ----
    if (tid < NW) {
        const float q = 0.01f;
        int ew = 0;
        float c1r = 0.f, c1g = 0.f, c1b = 0.f;
        float c2r = 0.f, c2g = 0.f, c2b = 0.f, cnt = 0.f;
        const int j0 = tid * RNG;
        for (int j = j0; j < j0 + RNG; ++j) {
            const float cr = rec[j][6], cg = rec[j][7], cb = rec[j][8];
            if (sfar[j]) {
                c2r = fmaf(cnt, cr, c2r);
                c2g = fmaf(cnt, cg, c2g);
                c2b = fmaf(cnt, cb, c2b);
                c1r += cr; c1g += cg; c1b += cb;
                cnt += 1.0f;
            } else {
                if (cnt > 0.0f) {
                    u64* p = ent[tid][ew];
                    p[0] = pk(q * c1r, q * c1r);
                    p[1] = pk(q * c1g, q * c1g);
                    p[2] = pk(q * c1b, q * c1b);
                    p[3] = pk(-q * q * c2r, -q * q * c2r);
                    p[4] = pk(-q * q * c2g, -q * q * c2g);
                    p[5] = pk(-q * q * c2b, -q * q * c2b);
                    p[6] = pk(-q * cnt, -q * cnt);
                    p[9] = 0ull; ++ew;
                    c1r = c1g = c1b = c2r = c2g = c2b = cnt = 0.f;
                }
                u64* p = ent[tid][ew];
                #pragma unroll
                for (int r = 0; r < 9; ++r) { const float v = rec[j][r]; p[r] = pk(v, v); }
                p[9] = 1ull; ++ew;
            }
        }
        if (cnt > 0.0f) {
            u64* p = ent[tid][ew];
            p[0] = pk(q * c1r, q * c1r);
            p[1] = pk(q * c1g, q * c1g);
            p[2] = pk(q * c1b, q * c1b);
            p[3] = pk(-q * q * c2r, -q * q * c2r);
            p[4] = pk(-q * q * c2g, -q * q * c2g);
            p[5] = pk(-q * q * c2b, -q * q * c2b);
            p[6] = pk(-q * cnt, -q * cnt);
            p[9] = 0ull; ++ew;
        }
        sne[tid] = ew;
    }
    __syncthreads();

    // ---- compact into global stream ----
    if (tid == 0) {
        int a = 0;
        #pragma unroll
        for (int w = 0; w < NW; ++w) { soff[w] = a; a += sne[w]; }
        soff[NW] = a;
        g_cnt[t] = a;
    }
    __syncthreads();

    for (int w = 0; w < NW; ++w) {
        const int n = (soff[w + 1] - soff[w]) * ESTR;
        u64* dst = g_ent[t] + soff[w] * ESTR;
        const u64* src = &ent[w][0][0];
        for (int i = tid; i < n; i += 256) dst[i] = src[i];
    }
}

// ===================== Kernel B: pixel mainloop =====================
__global__ __launch_bounds__(128, 7)
void render_kernel(float* __restrict__ out)
{
    __shared__ u64 sent[TMAX * ESTR];

    const int bid = blockIdx.x;
    const int t   = bid >> 4;        // tile
    const int s   = bid & 15;        // 4-row segment
    const int tx  = t & 7;
    const int ty  = t >> 3;
    const int tid = threadIdx.x;

    const int cnt = g_cnt[t];
    const int nu  = cnt * ESTR;
    const u64* gsrc = g_ent[t];
    for (int i = tid; i < nu; i += 128) sent[i] = gsrc[i];
    __syncthreads();

    // 2 px/thread: column lx, rows gy, gy+1
    const int lx = tid & 63;
    const int ry = tid >> 6;
    const float px = (float)(tx * 64 + lx) + 0.5f;
    const float py = (float)(ty * 64 + s * 4 + ry * 2) + 0.5f;
    const u64 px2 = pk(px, px);
    const u64 py2 = pk(py, py + 1.0f);
    const u64 m1  = pk(-1.0f, -1.0f);

    u64 aR = 0, aG = 0, aB = 0;
    u64 tr = pk(1.0f, 1.0f);

    const u64* p = sent;
    for (int e = 0; e < cnt; ++e, p += ESTR) {
        if (p[9]) {
            // near: full evaluation
            const u64 dx2 = fadd2(px2, p[0]);
            const u64 t0  = fmul2(p[2], dx2);
            const u64 u2  = ffma2(t0, dx2, p[5]);     // k1*dx^2 + lop
            const u64 kx2 = fmul2(p[3], dx2);         // k2*dx
            const u64 dy2 = fadd2(py2, p[1]);
            const u64 q2  = ffma2(p[4], dy2, kx2);
            const u64 pw  = ffma2(dy2, q2, u2);
            F2U P; P.u = pw;
            F2U al;
            al.f.x = clampa(ex2f(P.f.x));
            al.f.y = clampa(ex2f(P.f.y));
            const u64 wv = fmul2(al.u, tr);           // alpha*(1 - sum_prev)
            tr = ffma2(al.u, m1, tr);                 // trans -= alpha (cumsum)
            aR = ffma2(wv, p[6], aR);
            aG = ffma2(wv, p[7], aG);
            aB = ffma2(wv, p[8], aB);
        } else {
            // run: acc += q*T0*C1 - q^2*C2 ; T -= q*m
            aR = ffma2(tr, p[0], aR);  aR = fadd2(aR, p[3]);
            aG = ffma2(tr, p[1], aG);  aG = fadd2(aG, p[4]);
            aB = ffma2(tr, p[2], aB);  aB = fadd2(aB, p[5]);
            tr = fadd2(tr, p[6]);
        }
    }

    // write 2 pixels
    const int gx = tx * 64 + lx;
    const int gy = ty * 64 + s * 4 + ry * 2;
    F2U R, G, B; R.u = aR; G.u = aG; B.u = aB;
    float* o = out + ((size_t)gy * WIMG + gx) * 3;
    o[0] = R.f.x; o[1] = G.f.x; o[2] = B.f.x;
    o += WIMG * 3;
    o[0] = R.f.y; o[1] = G.f.y; o[2] = B.f.y;
}

extern "C" void kernel_launch(void* const* d_in, const int* in_sizes, int n_in,
                              void* d_out, int out_size)
{
    const float* mu   = (const float*)d_in[0];
    const float* cov  = (const float*)d_in[1];
    const float* opac = (const float*)d_in[2];
    const float* col  = (const float*)d_in[3];
    const int*   tidx = (const int*)  d_in[4];
    float* out = (float*)d_out;

    build_kernel<<<64, 256>>>(mu, cov, opac, col, tidx);
    render_kernel<<<1024, 128>>>(out);
}

// round 8
// speedup vs baseline: 4.0284x; 1.5478x over previous
#include <cuda_runtime.h>
#include <cuda_bf16.h>

// GaussianRender: 64 tiles (8x8) of 64x64 px, K=256 depth-sorted gaussians/tile.
// alpha = clip(op*prob, 0.01, 0.99). Gaussians provably far from the whole tile
// (Schur bound: log2(a) <= lop + min(e*mdx^2/cov_xx, e*mdy^2/cov_yy)) contribute
// exactly alpha=0.01 everywhere; a run of m far gaussians has the closed form
//   acc += q*T0*S1 - q^2*S2,  T -= q*m   (S1=sum c, S2=sum pos*c, pixel-indep).
//
// Stream format: entry = [merged run-prefix(7 u64) | near gaussian(9 u64)],
// 128B. Trailing gap uses a DUMMY near (k=0, colors=0: only corrupts tr after
// its last use) -> render mainloop is branch-free and uniform, nnear+1 entries.
//
// Kernel A (64 CTAs x 256): ballot/scan finds nears, warp-per-gap shfl
// reduction builds entries. Fully parallel, no serial walker.
// Kernel B (1024 CTAs x 128): LDS.128 mainloop, packed f32x2, 2 px/thread.

#define KG     256
#define WIMG   512
#define EU     16            // u64 per entry
#define EMAXT  (KG + 1)      // worst-case entries per tile

typedef unsigned long long u64;
union F2U { float2 f; u64 u; };

__device__ __align__(16) u64 g_ent[64][EMAXT * EU];
__device__ int g_cnt[64];

__device__ __forceinline__ u64 pk(float a, float b) { F2U t; t.f = make_float2(a, b); return t.u; }
__device__ __forceinline__ u64 ffma2(u64 a, u64 b, u64 c) {
    u64 d; asm("fma.rn.f32x2 %0, %1, %2, %3;" : "=l"(d) : "l"(a), "l"(b), "l"(c)); return d;
}
__device__ __forceinline__ u64 fmul2(u64 a, u64 b) {
    u64 d; asm("mul.rn.f32x2 %0, %1, %2;" : "=l"(d) : "l"(a), "l"(b)); return d;
}
__device__ __forceinline__ u64 fadd2(u64 a, u64 b) {
    u64 d; asm("add.rn.f32x2 %0, %1, %2;" : "=l"(d) : "l"(a), "l"(b)); return d;
}
__device__ __forceinline__ float ex2f(float x) {
    float y; asm("ex2.approx.f32 %0, %1;" : "=f"(y) : "f"(x)); return y;
}
__device__ __forceinline__ float lg2f(float x) {
    float y; asm("lg2.approx.f32 %0, %1;" : "=f"(y) : "f"(x)); return y;
}
__device__ __forceinline__ float clampa(float a) { return fminf(fmaxf(a, 0.01f), 0.99f); }

// ===================== Kernel A: per-tile stream build =====================
__global__ __launch_bounds__(256, 4)
void build_kernel(const float* __restrict__ mu,
                  const float* __restrict__ cov,
                  const float* __restrict__ opac,
                  const float* __restrict__ col,
                  const int*   __restrict__ tidx)
{
    // rec: [0]=-mx [1]=-my [2]=k1 [3]=k2 [4]=k3 [5]=lop [6]=cr [7]=cg [8]=cb
    __shared__ float        rec[KG][9];
    __shared__ unsigned int wmask[8];
    __shared__ int          sbase[8];
    __shared__ int          snears[KG];
    __shared__ int          s_nn;

    const int t    = blockIdx.x;     // tile 0..63
    const int tx   = t & 7;
    const int ty   = t >> 3;
    const int tid  = threadIdx.x;    // 0..255 (= gaussian slot j)
    const int lane = tid & 31;
    const int warp = tid >> 5;

    const float x0 = (float)(tx * 64) + 0.5f, x1 = x0 + 63.0f;
    const float y0 = (float)(ty * 64) + 0.5f, y1 = y0 + 63.0f;

    // ---- phase 1: records + tight conservative far test ----
    bool isNear;
    {
        const int g = tidx[t * KG + tid];
        const float4 cv = *(const float4*)(cov + g * 4);
        const float2 m  = *(const float2*)(mu + g * 2);
        const float det = fmaxf(fmaf(cv.x, cv.w, -cv.y * cv.z), 1e-6f);
        const float inv = 1.0f / det;
        const float e  = -0.7213475204444817f;   // -0.5 * log2(e)
        const float k1 = e * cv.w * inv;
        const float k2 = -e * (cv.y + cv.z) * inv;
        const float k3 = e * cv.x * inv;
        const float lop = lg2f(opac[g]);

        const float dlo = x0 - m.x, dhi = x1 - m.x;
        const float mdx = fmaxf(fmaxf(dlo, -dhi), 0.0f);
        const float elo = y0 - m.y, ehi = y1 - m.y;
        const float mdy = fmaxf(fmaxf(elo, -ehi), 0.0f);
        const float bx = __fdividef(e * mdx * mdx, cv.x);
        const float by = __fdividef(e * mdy * mdy, cv.w);
        const float bnd = fminf(bx, by) + lop;
        isNear = !(bnd < (-6.6438561897747395f - 0.01f));

        rec[tid][0] = -m.x;  rec[tid][1] = -m.y;
        rec[tid][2] = k1;    rec[tid][3] = k2;
        rec[tid][4] = k3;    rec[tid][5] = lop;
        rec[tid][6] = col[g * 3 + 0];
        rec[tid][7] = col[g * 3 + 1];
        rec[tid][8] = col[g * 3 + 2];
    }
    const unsigned int mask = __ballot_sync(0xffffffffu, isNear);
    if (lane == 0) wmask[warp] = mask;
    __syncthreads();

    // ---- phase 2: scan -> ordered near list ----
    if (tid == 0) {
        int a = 0;
        #pragma unroll
        for (int w = 0; w < 8; ++w) { sbase[w] = a; a += __popc(wmask[w]); }
        s_nn = a;
    }
    __syncthreads();
    if (isNear) {
        const int rank = sbase[warp] + __popc(mask & ((1u << lane) - 1u));
        snears[rank] = tid;
    }
    __syncthreads();

    // ---- phase 3+4: one warp per entry; reduce gap sums, write entry ----
    const int nn = s_nn;                 // entries = nn + 1
    for (int i = warp; i <= nn; i += 8) {
        const int start = (i == 0) ? 0 : snears[i - 1] + 1;
        const int end   = (i < nn) ? snears[i] - 1 : KG - 1;

        float S1r = 0.f, S1g = 0.f, S1b = 0.f;
        float S2r = 0.f, S2g = 0.f, S2b = 0.f;
        for (int j = start + lane; j <= end; j += 32) {
            const float rel = (float)(j - start);
            const float cr = rec[j][6], cg = rec[j][7], cb = rec[j][8];
            S1r += cr; S1g += cg; S1b += cb;
            S2r = fmaf(rel, cr, S2r);
            S2g = fmaf(rel, cg, S2g);
            S2b = fmaf(rel, cb, S2b);
        }
        #pragma unroll
        for (int o = 16; o >= 1; o >>= 1) {
            S1r += __shfl_xor_sync(0xffffffffu, S1r, o);
            S1g += __shfl_xor_sync(0xffffffffu, S1g, o);
            S1b += __shfl_xor_sync(0xffffffffu, S1b, o);
            S2r += __shfl_xor_sync(0xffffffffu, S2r, o);
            S2g += __shfl_xor_sync(0xffffffffu, S2g, o);
            S2b += __shfl_xor_sync(0xffffffffu, S2b, o);
        }
        if (lane == 0) {
            u64* p = g_ent[t] + i * EU;
            const float q = 0.01f;
            const float cm = (float)(end - start + 1);
            p[0] = pk(q * S1r, q * S1r);
            p[1] = pk(q * S1g, q * S1g);
            p[2] = pk(q * S1b, q * S1b);
            p[3] = pk(-q * q * S2r, -q * q * S2r);
            p[4] = pk(-q * q * S2g, -q * q * S2g);
            p[5] = pk(-q * q * S2b, -q * q * S2b);
            p[6] = pk(-q * cm, -q * cm);
            if (i < nn) {
                const int j = snears[i];
                #pragma unroll
                for (int r = 0; r < 9; ++r) { const float v = rec[j][r]; p[7 + r] = pk(v, v); }
            } else {
                // dummy near: k=0, lop=0, mu=0, colors=0 -> acc unchanged,
                // tr corrupted only after its last use.
                #pragma unroll
                for (int r = 0; r < 9; ++r) p[7 + r] = 0ull;
            }
        }
    }
    if (tid == 0) g_cnt[t] = nn + 1;
}

// ===================== Kernel B: branch-free pixel mainloop =====================
// entry as ulonglong2[8]:
//  v0={s1r,s1g} v1={s1b,s2r} v2={s2g,s2b} v3={scnt,-mx}
//  v4={-my,k1}  v5={k2,k3}   v6={lop,cr}  v7={cg,cb}
#define ENT_BODY(P)                                                         \
    {                                                                       \
        const ulonglong2 v0 = (P)[0], v1 = (P)[1], v2 = (P)[2], v3 = (P)[3];\
        const ulonglong2 v4 = (P)[4], v5 = (P)[5], v6 = (P)[6], v7 = (P)[7];\
        /* run prefix: acc += T0*s1 + s2 ; tr += scnt */                    \
        aR = ffma2(tr, v0.x, aR);  aR = fadd2(aR, v1.y);                    \
        aG = ffma2(tr, v0.y, aG);  aG = fadd2(aG, v2.x);                    \
        aB = ffma2(tr, v1.x, aB);  aB = fadd2(aB, v2.y);                    \
        tr = fadd2(tr, v3.x);                                               \
        /* near gaussian */                                                 \
        const u64 dx2 = fadd2(px2, v3.y);                                   \
        const u64 t0  = fmul2(v4.y, dx2);                                   \
        const u64 u2  = ffma2(t0, dx2, v6.x);     /* k1*dx^2 + lop */       \
        const u64 kx2 = fmul2(v5.x, dx2);         /* k2*dx */               \
        const u64 dy2 = fadd2(py2, v4.x);                                   \
        const u64 q2  = ffma2(v5.y, dy2, kx2);                              \
        const u64 pw  = ffma2(dy2, q2, u2);                                 \
        F2U PW; PW.u = pw;                                                  \
        F2U al;                                                             \
        al.f.x = clampa(ex2f(PW.f.x));                                      \
        al.f.y = clampa(ex2f(PW.f.y));                                      \
        const u64 wv = fmul2(al.u, tr);           /* alpha*(1-sum_prev) */  \
        tr = ffma2(al.u, m1, tr);                 /* trans -= alpha */      \
        aR = ffma2(wv, v6.y, aR);                                           \
        aG = ffma2(wv, v7.x, aG);                                           \
        aB = ffma2(wv, v7.y, aB);                                           \
    }

__global__ __launch_bounds__(128, 8)
void render_kernel(float* __restrict__ out)
{
    __shared__ __align__(16) u64 sent[64 * EU];   // 8 KB: up to 64 entries

    const int bid = blockIdx.x;
    const int t   = bid >> 4;        // tile
    const int s   = bid & 15;        // 4-row segment
    const int tx  = t & 7;
    const int ty  = t >> 3;
    const int tid = threadIdx.x;

    const int cnt = g_cnt[t];
    const u64* gsrc = g_ent[t];
    const int ns = (cnt < 64) ? cnt : 64;
    {
        const ulonglong2* s2p = (const ulonglong2*)gsrc;
        ulonglong2* d2p = (ulonglong2*)sent;
        const int n2 = ns * (EU / 2);
        for (int i = tid; i < n2; i += 128) d2p[i] = s2p[i];
    }
    __syncthreads();

    // 2 px/thread: column lx, rows gy, gy+1
    const int lx = tid & 63;
    const int ry = tid >> 6;
    const float px = (float)(tx * 64 + lx) + 0.5f;
    const float py = (float)(ty * 64 + s * 4 + ry * 2) + 0.5f;
    const u64 px2 = pk(px, px);
    const u64 py2 = pk(py, py + 1.0f);
    const u64 m1  = pk(-1.0f, -1.0f);

    u64 aR = 0, aG = 0, aB = 0;
    u64 tr = pk(1.0f, 1.0f);

    const ulonglong2* p = (const ulonglong2*)sent;
    for (int e = 0; e < ns; ++e, p += 8) ENT_BODY(p)

    if (cnt > 64) {   // safety overflow path (not taken for this input)
        const ulonglong2* pg = (const ulonglong2*)(gsrc + 64 * EU);
        for (int e = 64; e < cnt; ++e, pg += 8) ENT_BODY(pg)
    }

    // write 2 pixels
    const int gx = tx * 64 + lx;
    const int gy = ty * 64 + s * 4 + ry * 2;
    F2U R, G, B; R.u = aR; G.u = aG; B.u = aB;
    float* o = out + ((size_t)gy * WIMG + gx) * 3;
    o[0] = R.f.x; o[1] = G.f.x; o[2] = B.f.x;
    o += WIMG * 3;
    o[0] = R.f.y; o[1] = G.f.y; o[2] = B.f.y;
}

extern "C" void kernel_launch(void* const* d_in, const int* in_sizes, int n_in,
                              void* d_out, int out_size)
{
    const float* mu   = (const float*)d_in[0];
    const float* cov  = (const float*)d_in[1];
    const float* opac = (const float*)d_in[2];
    const float* col  = (const float*)d_in[3];
    const int*   tidx = (const int*)  d_in[4];
    float* out = (float*)d_out;

    build_kernel<<<64, 256>>>(mu, cov, opac, col, tidx);
    render_kernel<<<1024, 128>>>(out);
}